// round 5
// baseline (speedup 1.0000x reference)
#include <cuda_runtime.h>
#include <math.h>

#define NKEY 128            // NUM_IMGS(8) * NUM_CLASSES(16)
#define NUM_CLASSES 16
#define NT 256              // threads per block
#define CAP 1024            // max group size held in smem (mean ~64, huge margin)

// cross-call state (zero at load; self-resetting each call)
__device__ float g_acc;
__device__ int   g_done;

__global__ __launch_bounds__(NT)
void k_fused(const float* __restrict__ preds,
             const float* __restrict__ scores,
             const int*   __restrict__ labels,
             const int*   __restrict__ batch,
             float* __restrict__ out, int n, float inv_n) {
    __shared__ float4 sa[CAP];      // {cx, cy, inv(2sig^2), score}
    __shared__ float2 sv[CAP];      // {cos4t, sin4t}
    __shared__ int    s_cnt;
    __shared__ float  red[NT / 32];

    const int mykey = blockIdx.x;   // one block per (batch, class) key
    const int t     = threadIdx.x;
    const int lane  = t & 31;
    const int wib   = t >> 5;

    if (t == 0) s_cnt = 0;
    __syncthreads();

    // ---- P1: stream keys, gather my group's members into smem ----
    for (int i = t; i < n; i += NT) {
        int key = batch[i] * NUM_CLASSES + labels[i];
        if (key == mykey) {
            const float* p = preds + 5 * i;
            float cx = p[0], cy = p[1], w = p[2], h = p[3], th = p[4];
            float scale = fminf(fmaxf(sqrtf(w * h), 16.0f), 800.0f);
            float sig = 2.0f * scale;                 // K_RADIUS = 2
            float inv = 1.0f / (2.0f * sig * sig);
            float sn, cs;
            sincosf(4.0f * th, &sn, &cs);
            int idx = atomicAdd(&s_cnt, 1);
            if (idx < CAP) {
                sa[idx] = make_float4(cx, cy, inv, scores[i]);  // SCORE_ALPHA = 1
                sv[idx] = make_float2(cs, sn);
            }
        }
    }
    __syncthreads();
    int g = min(s_cnt, CAP);

    // ---- P2: O(g^2) sweep entirely in smem; warp-per-point ----
    float chaos_sum = 0.0f;                           // valid on lane 0
    for (int p = wib; p < g; p += NT / 32) {
        float4 a = sa[p];
        float den = 0.0f, nx = 0.0f, ny = 0.0f;
        for (int j = lane; j < g; j += 32) {
            float4 b = sa[j];
            float2 v = sv[j];
            float dx = a.x - b.x;
            float dy = a.y - b.y;
            float wgt = __expf(-(dx * dx + dy * dy) * a.z) * b.w;
            den += wgt;
            nx  += wgt * v.x;
            ny  += wgt * v.y;
        }
        #pragma unroll
        for (int o = 16; o; o >>= 1) {
            den += __shfl_xor_sync(0xffffffffu, den, o);
            nx  += __shfl_xor_sync(0xffffffffu, nx, o);
            ny  += __shfl_xor_sync(0xffffffffu, ny, o);
        }
        if (lane == 0) chaos_sum += 1.0f - sqrtf(nx * nx + ny * ny) / den;
    }

    // ---- P3: block reduce, accumulate, last-block ticket writes out ----
    if (lane == 0) red[wib] = chaos_sum;
    __syncthreads();
    if (t < NT / 32) {
        float v = red[t];
        v += __shfl_xor_sync(0xffu, v, 4);
        v += __shfl_xor_sync(0xffu, v, 2);
        v += __shfl_xor_sync(0xffu, v, 1);
        if (t == 0) {
            atomicAdd(&g_acc, v);
            __threadfence();
            int tk = atomicAdd(&g_done, 1);
            if (tk == NKEY - 1) {                     // last block: finalize + reset
                float tot = atomicAdd(&g_acc, 0.0f);  // atomic read-after-all-adds
                *out = tot * inv_n;                   // LOSS_WEIGHT = 1
                g_acc = 0.0f;
                g_done = 0;
            }
        }
    }
}

extern "C" void kernel_launch(void* const* d_in, const int* in_sizes, int n_in,
                              void* d_out, int out_size) {
    const float* preds  = (const float*)d_in[0];
    const float* scores = (const float*)d_in[1];
    const int*   labels = (const int*)d_in[2];
    const int*   batch  = (const int*)d_in[3];
    float* out = (float*)d_out;
    int n = in_sizes[1];                 // pos_scores element count = N

    k_fused<<<NKEY, NT>>>(preds, scores, labels, batch, out, n, 1.0f / (float)n);
}

// round 6
// speedup vs baseline: 1.7026x; 1.7026x over previous
#include <cuda_runtime.h>
#include <math.h>

#define NKEY 128            // NUM_IMGS(8) * NUM_CLASSES(16)
#define NUM_CLASSES 16
#define CAP 256             // slots per key (mean occupancy 64; huge margin)
#define NT2 256             // threads per block, sweep kernel

// ---- scratch: fixed-slot layout, no scan needed ----
__device__ float4 g_a[NKEY * CAP];   // {cx, cy, inv(2sig^2), score}
__device__ float2 g_v[NKEY * CAP];   // {cos4t, sin4t}
__device__ int    g_cnt[NKEY];       // zero at load; reset by K2 each call

// K1: per-point precompute + direct slotted scatter (no histogram/scan)
__global__ __launch_bounds__(128)
void k_pre(const float* __restrict__ preds,
           const float* __restrict__ scores,
           const int*   __restrict__ labels,
           const int*   __restrict__ batch,
           float* __restrict__ out, int n) {
    int i = blockIdx.x * 128 + threadIdx.x;
    if (i == 0) *out = 0.0f;
    if (i >= n) return;
    const float* p = preds + 5 * i;
    float cx = p[0], cy = p[1], w = p[2], h = p[3], th = p[4];
    float scale = fminf(fmaxf(sqrtf(w * h), 16.0f), 800.0f);
    float sig = 2.0f * scale;                  // K_RADIUS = 2
    float inv = 1.0f / (2.0f * sig * sig);
    float sn, cs;
    sincosf(4.0f * th, &sn, &cs);
    int key = batch[i] * NUM_CLASSES + labels[i];
    int slot = atomicAdd(&g_cnt[key], 1);
    if (slot < CAP) {
        int idx = key * CAP + slot;
        g_a[idx] = make_float4(cx, cy, inv, scores[i]);   // SCORE_ALPHA = 1
        g_v[idx] = make_float2(cs, sn);
    }
}

// K2: one block per key — smem sweep + partial accumulate + cursor reset
__global__ __launch_bounds__(NT2)
void k_main(float* __restrict__ out, float inv_n) {
    __shared__ float4 sa[CAP];
    __shared__ float2 sv[CAP];
    __shared__ float  red[NT2 / 32];

    const int key  = blockIdx.x;
    const int t    = threadIdx.x;
    const int lane = t & 31;
    const int wib  = t >> 5;

    int g = min(g_cnt[key], CAP);

    // cooperative load of group into smem (coalesced)
    const int base = key * CAP;
    for (int j = t; j < g; j += NT2) {
        sa[j] = g_a[base + j];
        sv[j] = g_v[base + j];
    }
    __syncthreads();
    if (t == 0) g_cnt[key] = 0;        // self-reset for next replay

    // warp-per-point sweep
    float chaos_sum = 0.0f;            // valid on lane 0
    for (int p = wib; p < g; p += NT2 / 32) {
        float4 a = sa[p];
        float den = 0.0f, nx = 0.0f, ny = 0.0f;
        for (int j = lane; j < g; j += 32) {
            float4 b = sa[j];
            float2 v = sv[j];
            float dx = a.x - b.x;
            float dy = a.y - b.y;
            float wgt = __expf(-(dx * dx + dy * dy) * a.z) * b.w;
            den += wgt;
            nx  += wgt * v.x;
            ny  += wgt * v.y;
        }
        #pragma unroll
        for (int o = 16; o; o >>= 1) {
            den += __shfl_xor_sync(0xffffffffu, den, o);
            nx  += __shfl_xor_sync(0xffffffffu, nx, o);
            ny  += __shfl_xor_sync(0xffffffffu, ny, o);
        }
        if (lane == 0) chaos_sum += 1.0f - sqrtf(nx * nx + ny * ny) / den;
    }

    // block reduce + one atomicAdd per block
    if (lane == 0) red[wib] = chaos_sum;
    __syncthreads();
    if (t < NT2 / 32) {
        float v = red[t];
        v += __shfl_xor_sync(0xffu, v, 4);
        v += __shfl_xor_sync(0xffu, v, 2);
        v += __shfl_xor_sync(0xffu, v, 1);
        if (t == 0) atomicAdd(out, v * inv_n);   // LOSS_WEIGHT = 1
    }
}

extern "C" void kernel_launch(void* const* d_in, const int* in_sizes, int n_in,
                              void* d_out, int out_size) {
    const float* preds  = (const float*)d_in[0];
    const float* scores = (const float*)d_in[1];
    const int*   labels = (const int*)d_in[2];
    const int*   batch  = (const int*)d_in[3];
    float* out = (float*)d_out;
    int n = in_sizes[1];                 // pos_scores element count = N

    k_pre<<<(n + 127) / 128, 128>>>(preds, scores, labels, batch, out, n);
    k_main<<<NKEY, NT2>>>(out, 1.0f / (float)n);
}

// round 7
// speedup vs baseline: 1.8990x; 1.1154x over previous
#include <cuda_runtime.h>
#include <math.h>

#define NKEY 128            // NUM_IMGS(8) * NUM_CLASSES(16)
#define NUM_CLASSES 16
#define CAP 256             // slots per key (mean occupancy 64; huge margin)
#define NT2 256             // threads per block, sweep kernel

// ---- scratch: fixed-slot layout, no scan needed ----
__device__ float4 g_a[NKEY * CAP];   // {cx, cy, inv(2sig^2), score}
__device__ float2 g_v[NKEY * CAP];   // {cos4t, sin4t}
__device__ int    g_cnt[NKEY];       // zero at load; reset by K2 each call

// K1: per-point precompute + direct slotted scatter
__global__ __launch_bounds__(64)
void k_pre(const float* __restrict__ preds,
           const float* __restrict__ scores,
           const int*   __restrict__ labels,
           const int*   __restrict__ batch,
           float* __restrict__ out, int n) {
    int i = blockIdx.x * 64 + threadIdx.x;
    if (i == 0) *out = 0.0f;
    if (i >= n) return;
    const float* p = preds + 5 * i;
    float cx = p[0], cy = p[1], w = p[2], h = p[3], th = p[4];
    float scale = fminf(fmaxf(sqrtf(w * h), 16.0f), 800.0f);
    float sig = 2.0f * scale;                  // K_RADIUS = 2
    float inv = __fdividef(1.0f, 2.0f * sig * sig);
    float sn, cs;
    __sincosf(4.0f * th, &sn, &cs);            // |arg| <= 4*pi: MUFU path ok
    int key = batch[i] * NUM_CLASSES + labels[i];
    int slot = atomicAdd(&g_cnt[key], 1);
    if (slot < CAP) {
        int idx = key * CAP + slot;
        g_a[idx] = make_float4(cx, cy, inv, scores[i]);   // SCORE_ALPHA = 1
        g_v[idx] = make_float2(cs, sn);
    }
}

// K2 (PDL secondary): one block per key — smem sweep + partial accumulate
__global__ __launch_bounds__(NT2)
void k_main(float* __restrict__ out, float inv_n) {
    __shared__ float4 sa[CAP];
    __shared__ float2 sv[CAP];
    __shared__ float  red[NT2 / 32];

    const int key  = blockIdx.x;
    const int t    = threadIdx.x;
    const int lane = t & 31;
    const int wib  = t >> 5;

    // ramp/preamble overlaps with k_pre; gate before first dependent read
    cudaGridDependencySynchronize();

    int g = min(g_cnt[key], CAP);

    // cooperative load of group into smem (coalesced)
    const int base = key * CAP;
    for (int j = t; j < g; j += NT2) {
        sa[j] = g_a[base + j];
        sv[j] = g_v[base + j];
    }
    __syncthreads();
    if (t == 0) g_cnt[key] = 0;        // self-reset for next replay

    // warp-per-point sweep
    float chaos_sum = 0.0f;            // valid on lane 0
    for (int p = wib; p < g; p += NT2 / 32) {
        float4 a = sa[p];
        float den = 0.0f, nx = 0.0f, ny = 0.0f;
        for (int j = lane; j < g; j += 32) {
            float4 b = sa[j];
            float2 v = sv[j];
            float dx = a.x - b.x;
            float dy = a.y - b.y;
            float wgt = __expf(-(dx * dx + dy * dy) * a.z) * b.w;
            den += wgt;
            nx  += wgt * v.x;
            ny  += wgt * v.y;
        }
        #pragma unroll
        for (int o = 16; o; o >>= 1) {
            den += __shfl_xor_sync(0xffffffffu, den, o);
            nx  += __shfl_xor_sync(0xffffffffu, nx, o);
            ny  += __shfl_xor_sync(0xffffffffu, ny, o);
        }
        if (lane == 0) chaos_sum += 1.0f - sqrtf(nx * nx + ny * ny) / den;
    }

    // block reduce + one atomicAdd per block
    if (lane == 0) red[wib] = chaos_sum;
    __syncthreads();
    if (t < NT2 / 32) {
        float v = red[t];
        v += __shfl_xor_sync(0xffu, v, 4);
        v += __shfl_xor_sync(0xffu, v, 2);
        v += __shfl_xor_sync(0xffu, v, 1);
        if (t == 0) atomicAdd(out, v * inv_n);   // LOSS_WEIGHT = 1
    }
}

extern "C" void kernel_launch(void* const* d_in, const int* in_sizes, int n_in,
                              void* d_out, int out_size) {
    const float* preds  = (const float*)d_in[0];
    const float* scores = (const float*)d_in[1];
    const int*   labels = (const int*)d_in[2];
    const int*   batch  = (const int*)d_in[3];
    float* out = (float*)d_out;
    int n = in_sizes[1];                 // pos_scores element count = N

    k_pre<<<(n + 63) / 64, 64>>>(preds, scores, labels, batch, out, n);

    // k_main as PDL secondary: ramp overlaps k_pre's execution
    cudaLaunchConfig_t cfg = {};
    cfg.gridDim  = dim3(NKEY, 1, 1);
    cfg.blockDim = dim3(NT2, 1, 1);
    cfg.dynamicSmemBytes = 0;
    cfg.stream = 0;                      // legacy default stream (capture target)
    cudaLaunchAttribute attr[1];
    attr[0].id = cudaLaunchAttributeProgrammaticStreamSerialization;
    attr[0].val.programmaticStreamSerializationAllowed = 1;
    cfg.attrs = attr;
    cfg.numAttrs = 1;
    float inv_n = 1.0f / (float)n;
    cudaLaunchKernelEx(&cfg, k_main, out, inv_n);
}